// round 2
// baseline (speedup 1.0000x reference)
#include <cuda_runtime.h>
#include <cstdint>

#define SRC_LEN 512
#define BATCH   64
#define HIDDEN  1024
#define EMBED   1024
#define NBLK    128           // persistent CTAs for the scan
#define JPB     8             // HIDDEN / NBLK output columns per CTA

// Scratch (static __device__ arrays: allowed, no runtime allocation)
__device__ float    g_xproj[SRC_LEN * HIDDEN * BATCH];   // [t][j][b]  (128MB)
__device__ float    g_h[2][HIDDEN * BATCH];              // ping-pong, [j*64+b] (transposed)
__device__ unsigned g_bar;

typedef unsigned long long ull;

__device__ __forceinline__ ull pk2(float x, float y) {
    ull r; asm("mov.b64 %0, {%1, %2};" : "=l"(r) : "f"(x), "f"(y)); return r;
}
__device__ __forceinline__ void upk2(ull p, float& x, float& y) {
    asm("mov.b64 {%0, %1}, %2;" : "=f"(x), "=f"(y) : "l"(p));
}
__device__ __forceinline__ ull ffma2(ull a, ull b, ull c) {
    ull d; asm("fma.rn.f32x2 %0, %1, %2, %3;" : "=l"(d) : "l"(a), "l"(b), "l"(c)); return d;
}

// ---------------------------------------------------------------------------
// Reset barrier counter + zero h0 each launch (graph-replay deterministic)
// ---------------------------------------------------------------------------
__global__ void init_kernel() {
    unsigned i = blockIdx.x * blockDim.x + threadIdx.x;
    if (i == 0) g_bar = 0u;
    if (i < HIDDEN * BATCH) g_h[0][i] = 0.0f;
}

// ---------------------------------------------------------------------------
// Stage 1: x_proj[t][j][b] = sum_e emb[src[b,t]][e] * Wxh[j][e] + bxh[j]
// Fused gather + tiled SGEMM. Tile: M=64 (== one t, m-dim is b), N=64, K=16.
// 256 threads, 4x4 micro-tile per thread, f32x2 packed FMAs.
// ---------------------------------------------------------------------------
__global__ __launch_bounds__(256) void xproj_kernel(
    const int*   __restrict__ src,
    const float* __restrict__ emb,
    const float* __restrict__ Wxh,
    const float* __restrict__ bxh)
{
    __shared__ __align__(16) float Ast[16][64];   // [kk][b]
    __shared__ __align__(16) float Bst[16][64];   // [kk][j]

    const int t   = blockIdx.x;          // 0..511
    const int jt  = blockIdx.y * 64;     // column tile base
    const int tid = threadIdx.x;
    const int lrow = tid >> 2;           // 0..63 (b for A, j for B)
    const int ev   = tid & 3;            // which 4-float chunk of the k-slice
    const int tx   = tid & 15;           // j micro-tile group
    const int ty   = tid >> 4;           // b micro-tile group

    const float* arow = emb + (size_t)__ldg(src + lrow * SRC_LEN + t) * EMBED + ev * 4;
    const float* brow = Wxh + (size_t)(jt + lrow) * EMBED + ev * 4;

    ull acc[4][2];
#pragma unroll
    for (int i = 0; i < 4; ++i) { acc[i][0] = 0ull; acc[i][1] = 0ull; }

    for (int e0 = 0; e0 < EMBED; e0 += 16) {
        float4 a4 = *(const float4*)(arow + e0);
        float4 b4 = *(const float4*)(brow + e0);
        __syncthreads();
        Ast[ev*4+0][lrow] = a4.x; Ast[ev*4+1][lrow] = a4.y;
        Ast[ev*4+2][lrow] = a4.z; Ast[ev*4+3][lrow] = a4.w;
        Bst[ev*4+0][lrow] = b4.x; Bst[ev*4+1][lrow] = b4.y;
        Bst[ev*4+2][lrow] = b4.z; Bst[ev*4+3][lrow] = b4.w;
        __syncthreads();
#pragma unroll
        for (int kk = 0; kk < 16; ++kk) {
            float4     av = *(const float4*)    &Ast[kk][ty * 4];
            ulonglong2 bp = *(const ulonglong2*)&Bst[kk][tx * 4];   // (j0,j1),(j2,j3)
            ull pa;
            pa = pk2(av.x, av.x); acc[0][0]=ffma2(pa,bp.x,acc[0][0]); acc[0][1]=ffma2(pa,bp.y,acc[0][1]);
            pa = pk2(av.y, av.y); acc[1][0]=ffma2(pa,bp.x,acc[1][0]); acc[1][1]=ffma2(pa,bp.y,acc[1][1]);
            pa = pk2(av.z, av.z); acc[2][0]=ffma2(pa,bp.x,acc[2][0]); acc[2][1]=ffma2(pa,bp.y,acc[2][1]);
            pa = pk2(av.w, av.w); acc[3][0]=ffma2(pa,bp.x,acc[3][0]); acc[3][1]=ffma2(pa,bp.y,acc[3][1]);
        }
    }

    float c[4][4];
#pragma unroll
    for (int i = 0; i < 4; ++i) {
        upk2(acc[i][0], c[i][0], c[i][1]);
        upk2(acc[i][1], c[i][2], c[i][3]);
    }
    // write [t][j][b], vectorized along b
    float* ob = g_xproj + (size_t)t * (HIDDEN*BATCH) + (size_t)(jt + tx*4) * BATCH + ty * 4;
#pragma unroll
    for (int jq = 0; jq < 4; ++jq) {
        float bj = __ldg(bxh + jt + tx*4 + jq);
        float4 v = make_float4(c[0][jq]+bj, c[1][jq]+bj, c[2][jq]+bj, c[3][jq]+bj);
        *(float4*)(ob + jq * BATCH) = v;
    }
}

// ---------------------------------------------------------------------------
// Stage 2: persistent RNN scan.
// 128 CTAs x 512 threads. CTA owns 8 output columns; W slice in SMEM [k][j].
// Thread (b = tid&63, q = tid>>6) accumulates k in [q*128, q*128+128) for all
// 8 columns; SMEM reduction over q; tanh; write transposed h; grid barrier.
// h read via __ldcg (L2 coherence point; L1 would be stale across ping-pong).
// ---------------------------------------------------------------------------
__global__ __launch_bounds__(512, 1) void rnn_scan_kernel(
    const float* __restrict__ Whh, float* __restrict__ out)
{
    __shared__ __align__(16) float Wt[HIDDEN * JPB];       // [k*8 + j]  32KB
    __shared__ __align__(16) float red[8][BATCH][JPB];     // 16KB

    const int tid   = threadIdx.x;
    const int jbase = blockIdx.x * JPB;

    // Load W_hh rows jbase..jbase+7, transposed to [k][j] for LDS.128 broadcast
    for (int idx = tid; idx < HIDDEN * JPB; idx += 512) {
        int j = idx >> 10, k = idx & (HIDDEN - 1);
        Wt[k * JPB + j] = __ldg(Whh + (size_t)(jbase + j) * HIDDEN + k);
    }
    __syncthreads();

    const int b  = tid & 63;
    const int q  = tid >> 6;       // 0..7 : k-slice
    const int k0 = q * 128;
    unsigned expected = 0;
    int   cur   = 0;
    float lastv = 0.0f;

    for (int t = 0; t < SRC_LEN; ++t) {
        const float* hprev = g_h[cur];
        float*       hnext = g_h[cur ^ 1];
        const float* hb = hprev + b;
        const float* wp = Wt + k0 * JPB;

        ull a0 = 0ull, a1 = 0ull, a2 = 0ull, a3 = 0ull;
#pragma unroll 8
        for (int k = 0; k < 128; ++k) {
            float hk = __ldcg(hb + (size_t)(k0 + k) * BATCH);
            ull pa = pk2(hk, hk);
            ulonglong2 wa = *(const ulonglong2*)(wp + k * JPB);      // (j0,j1),(j2,j3)
            ulonglong2 wb = *(const ulonglong2*)(wp + k * JPB + 4);  // (j4,j5),(j6,j7)
            a0 = ffma2(pa, wa.x, a0);
            a1 = ffma2(pa, wa.y, a1);
            a2 = ffma2(pa, wb.x, a2);
            a3 = ffma2(pa, wb.y, a3);
        }
        *(ulonglong2*)&red[q][b][0] = make_ulonglong2(a0, a1);
        *(ulonglong2*)&red[q][b][4] = make_ulonglong2(a2, a3);
        __syncthreads();

        // Reduce over the 8 k-slices: thread -> output (b, jbase + rj)
        const int rb = tid & 63, rj = tid >> 6;
        float s = red[0][rb][rj] + red[1][rb][rj] + red[2][rb][rj] + red[3][rb][rj]
                + red[4][rb][rj] + red[5][rb][rj] + red[6][rb][rj] + red[7][rb][rj];
        s += __ldg(g_xproj + (size_t)t * (HIDDEN*BATCH) + (size_t)(jbase + rj) * BATCH + rb);
        lastv = tanhf(s);
        __stcg(hnext + (jbase + rj) * BATCH + rb, lastv);

        // ---- grid-wide barrier (monotonic counter, reset per launch) ----
        expected += NBLK;
        __threadfence();          // release h writes to L2
        __syncthreads();
        if (tid == 0) {
            atomicAdd(&g_bar, 1u);
            while (*(volatile unsigned*)&g_bar < expected) { }
        }
        __syncthreads();
        cur ^= 1;
    }
    // thread's last reduced value IS output element (rb, jbase+rj)
    out[(tid & 63) * HIDDEN + jbase + (tid >> 6)] = lastv;
}

// ---------------------------------------------------------------------------
extern "C" void kernel_launch(void* const* d_in, const int* in_sizes, int n_in,
                              void* d_out, int out_size)
{
    const int*   src = (const int*)  d_in[0];
    const float* emb = (const float*)d_in[1];
    const float* Wxh = (const float*)d_in[2];
    const float* bxh = (const float*)d_in[3];
    const float* Whh = (const float*)d_in[4];
    float* out = (float*)d_out;

    init_kernel<<<256, 256>>>();
    xproj_kernel<<<dim3(SRC_LEN, HIDDEN / 64), 256>>>(src, emb, Wxh, bxh);
    rnn_scan_kernel<<<NBLK, 512>>>(Whh, out);
}

// round 3
// speedup vs baseline: 1.1623x; 1.1623x over previous
#include <cuda_runtime.h>
#include <cstdint>

#define SRC_LEN 512
#define BATCH   64
#define HIDDEN  1024
#define EMBED   1024
#define NBLK    128          // persistent CTAs for the scan (<=148: all resident)
#define JP      32           // j columns per scan CTA
#define BP      16           // batch per scan CTA

// Scratch (static __device__ arrays: allowed, no runtime allocation)
__device__ float    g_xproj[SRC_LEN * HIDDEN * BATCH];   // [t][j][b]
__device__ float    g_h[2][HIDDEN * BATCH];              // ping-pong, [k][b]
__device__ unsigned g_bar;

typedef unsigned long long ull;

__device__ __forceinline__ ull pk2(float x, float y) {
    ull r; asm("mov.b64 %0, {%1, %2};" : "=l"(r) : "f"(x), "f"(y)); return r;
}
__device__ __forceinline__ void upk2(ull p, float& x, float& y) {
    asm("mov.b64 {%0, %1}, %2;" : "=f"(x), "=f"(y) : "l"(p));
}
__device__ __forceinline__ ull ffma2(ull a, ull b, ull c) {
    ull d; asm("fma.rn.f32x2 %0, %1, %2, %3;" : "=l"(d) : "l"(a), "l"(b), "l"(c)); return d;
}

// ---------------------------------------------------------------------------
// Reset barrier counter + zero h0 each launch (graph-replay deterministic)
// ---------------------------------------------------------------------------
__global__ void init_kernel() {
    unsigned i = blockIdx.x * blockDim.x + threadIdx.x;
    if (i == 0) g_bar = 0u;
    if (i < HIDDEN * BATCH) g_h[0][i] = 0.0f;
}

// ---------------------------------------------------------------------------
// Stage 1: x_proj[t][j][b] = sum_e emb[src[b,t]][e] * Wxh[j][e] + bxh[j]
// Tile 64(b) x 128(j) x 16(k), 256 threads, 4b x 8j micro-tile (split quads),
// register-prefetch double buffer: ONE __syncthreads per K-slice.
// grid = (8 jt, 512 t): consecutive CTAs share t -> emb rows reused in L2.
// ---------------------------------------------------------------------------
__global__ __launch_bounds__(256) void xproj_kernel(
    const int*   __restrict__ src,
    const float* __restrict__ emb,
    const float* __restrict__ Wxh,
    const float* __restrict__ bxh)
{
    __shared__ __align__(16) float Ast[2][16][64];
    __shared__ __align__(16) float Bst[2][16][128];

    const int jt  = blockIdx.x;          // 0..7
    const int t   = blockIdx.y;          // 0..511
    const int tid = threadIdx.x;

    const int la_b = tid >> 2, la_e = tid & 3;    // A loader: 1 float4
    const int lb_j = tid >> 1, lb_e = tid & 1;    // B loader: 2 float4 (8 k)
    const int tx = tid & 15, ty = tid >> 4;       // micro-tile coords

    const float* arow = emb + (size_t)__ldg(src + la_b * SRC_LEN + t) * EMBED;
    const float* brow = Wxh + (size_t)(jt * 128 + lb_j) * EMBED;

    ull acc[4][4];                                 // [4 b][8 j as 4 f32x2]
#pragma unroll
    for (int i = 0; i < 4; ++i) { acc[i][0]=0; acc[i][1]=0; acc[i][2]=0; acc[i][3]=0; }

    // prologue: tile 0 -> regs -> smem[0]
    float4 pa  = *(const float4*)(arow + la_e * 4);
    float4 pb0 = *(const float4*)(brow + lb_e * 8);
    float4 pb1 = *(const float4*)(brow + lb_e * 8 + 4);
    Ast[0][la_e*4+0][la_b]=pa.x;  Ast[0][la_e*4+1][la_b]=pa.y;
    Ast[0][la_e*4+2][la_b]=pa.z;  Ast[0][la_e*4+3][la_b]=pa.w;
    Bst[0][lb_e*8+0][lb_j]=pb0.x; Bst[0][lb_e*8+1][lb_j]=pb0.y;
    Bst[0][lb_e*8+2][lb_j]=pb0.z; Bst[0][lb_e*8+3][lb_j]=pb0.w;
    Bst[0][lb_e*8+4][lb_j]=pb1.x; Bst[0][lb_e*8+5][lb_j]=pb1.y;
    Bst[0][lb_e*8+6][lb_j]=pb1.z; Bst[0][lb_e*8+7][lb_j]=pb1.w;

    const int NT = EMBED / 16;   // 64
    for (int i = 0; i < NT; ++i) {
        __syncthreads();
        const int cur = i & 1;
        if (i + 1 < NT) {
            const int e0 = (i + 1) * 16;
            pa  = *(const float4*)(arow + e0 + la_e * 4);
            pb0 = *(const float4*)(brow + e0 + lb_e * 8);
            pb1 = *(const float4*)(brow + e0 + lb_e * 8 + 4);
        }
#pragma unroll
        for (int kk = 0; kk < 16; ++kk) {
            float4     av = *(const float4*)    &Ast[cur][kk][ty * 4];
            ulonglong2 b0 = *(const ulonglong2*)&Bst[cur][kk][tx * 4];        // j quad0
            ulonglong2 b1 = *(const ulonglong2*)&Bst[cur][kk][64 + tx * 4];   // j quad1
            ull p;
            p = pk2(av.x, av.x); acc[0][0]=ffma2(p,b0.x,acc[0][0]); acc[0][1]=ffma2(p,b0.y,acc[0][1]);
                                 acc[0][2]=ffma2(p,b1.x,acc[0][2]); acc[0][3]=ffma2(p,b1.y,acc[0][3]);
            p = pk2(av.y, av.y); acc[1][0]=ffma2(p,b0.x,acc[1][0]); acc[1][1]=ffma2(p,b0.y,acc[1][1]);
                                 acc[1][2]=ffma2(p,b1.x,acc[1][2]); acc[1][3]=ffma2(p,b1.y,acc[1][3]);
            p = pk2(av.z, av.z); acc[2][0]=ffma2(p,b0.x,acc[2][0]); acc[2][1]=ffma2(p,b0.y,acc[2][1]);
                                 acc[2][2]=ffma2(p,b1.x,acc[2][2]); acc[2][3]=ffma2(p,b1.y,acc[2][3]);
            p = pk2(av.w, av.w); acc[3][0]=ffma2(p,b0.x,acc[3][0]); acc[3][1]=ffma2(p,b0.y,acc[3][1]);
                                 acc[3][2]=ffma2(p,b1.x,acc[3][2]); acc[3][3]=ffma2(p,b1.y,acc[3][3]);
        }
        if (i + 1 < NT) {
            const int nxt = cur ^ 1;
            Ast[nxt][la_e*4+0][la_b]=pa.x;  Ast[nxt][la_e*4+1][la_b]=pa.y;
            Ast[nxt][la_e*4+2][la_b]=pa.z;  Ast[nxt][la_e*4+3][la_b]=pa.w;
            Bst[nxt][lb_e*8+0][lb_j]=pb0.x; Bst[nxt][lb_e*8+1][lb_j]=pb0.y;
            Bst[nxt][lb_e*8+2][lb_j]=pb0.z; Bst[nxt][lb_e*8+3][lb_j]=pb0.w;
            Bst[nxt][lb_e*8+4][lb_j]=pb1.x; Bst[nxt][lb_e*8+5][lb_j]=pb1.y;
            Bst[nxt][lb_e*8+6][lb_j]=pb1.z; Bst[nxt][lb_e*8+7][lb_j]=pb1.w;
        }
    }

    // epilogue: c[b4][j8] + bias -> g_xproj[t][j][b] (float4 along b)
    float c[4][8];
#pragma unroll
    for (int i = 0; i < 4; ++i) {
        upk2(acc[i][0], c[i][0], c[i][1]); upk2(acc[i][1], c[i][2], c[i][3]);
        upk2(acc[i][2], c[i][4], c[i][5]); upk2(acc[i][3], c[i][6], c[i][7]);
    }
    float* obase = g_xproj + (size_t)t * (HIDDEN * BATCH) + ty * 4;
#pragma unroll
    for (int quad = 0; quad < 2; ++quad) {
#pragma unroll
        for (int jj = 0; jj < 4; ++jj) {
            const int j  = jt * 128 + quad * 64 + tx * 4 + jj;
            const float bj = __ldg(bxh + j);
            const int ci = quad * 4 + jj;
            float4 v = make_float4(c[0][ci]+bj, c[1][ci]+bj, c[2][ci]+bj, c[3][ci]+bj);
            *(float4*)(obase + (size_t)j * BATCH) = v;
        }
    }
}

// ---------------------------------------------------------------------------
// Stage 2: persistent RNN scan.
// 128 CTAs = 32 j-tiles x 4 b-tiles, 512 threads. CTA: 32 j cols x 16 batch.
// W slice (32x1024, transposed to [k][j]) in 128KB dynamic SMEM.
// Thread (b=tid&15, jg=(tid>>4)&3, q=tid>>6): k-slice of 128, 8 j columns.
// h read via __ldcg (64B warp-broadcast); SMEM reduction over 8 q-slices.
// ---------------------------------------------------------------------------
__global__ __launch_bounds__(512, 1) void rnn_scan_kernel(
    const float* __restrict__ Whh, float* __restrict__ out)
{
    extern __shared__ __align__(16) float sm[];
    float* Wt  = sm;              // [1024][32]  128KB
    float* red = sm + 32768;      // [8][16][36] 18KB (also 32x33 transpose stage)

    const int tid = threadIdx.x;
    const int jt  = blockIdx.x >> 2;    // 0..31
    const int bt  = blockIdx.x & 3;     // 0..3

    // ---- load W rows jt*32..+31, transposed to [k][32j], via 32x33 stage ----
    {
        const int kk = tid & 31, jh = tid >> 5;     // read coords (jh 0..15)
        const int j2 = tid & 31, kh = tid >> 5;     // write coords
        for (int k0 = 0; k0 < HIDDEN; k0 += 32) {
            red[jh * 33 + kk]        = __ldg(Whh + (size_t)(jt*32 + jh     ) * HIDDEN + k0 + kk);
            red[(jh + 16) * 33 + kk] = __ldg(Whh + (size_t)(jt*32 + jh + 16) * HIDDEN + k0 + kk);
            __syncthreads();
            Wt[(k0 + kh     ) * 32 + j2] = red[j2 * 33 + kh];
            Wt[(k0 + kh + 16) * 32 + j2] = red[j2 * 33 + kh + 16];
            __syncthreads();
        }
    }

    const int b  = tid & 15;
    const int jg = (tid >> 4) & 3;
    const int q  = tid >> 6;            // 0..7
    const int rb = tid & 15;            // reduction coords
    const int rj = tid >> 4;            // 0..31

    const float* wbase = Wt + q * 128 * 32 + jg * 8;
    const float* xp    = g_xproj + (size_t)(jt * 32 + rj) * BATCH + bt * 16 + rb;
    const int    hoff  = bt * 16 + b;
    const int    houto = (jt * 32 + rj) * BATCH + bt * 16 + rb;

    unsigned expected = 0;
    int   cur   = 0;
    float lastv = 0.0f;

    for (int t = 0; t < SRC_LEN; ++t) {
        const float xv = __ldcg(xp + (size_t)t * (HIDDEN * BATCH));   // prefetch early
        const float* hp = g_h[cur] + (size_t)q * 128 * BATCH + hoff;
        const float* wp = wbase;

        ull a0 = 0, a1 = 0, a2 = 0, a3 = 0;
#pragma unroll
        for (int ko = 0; ko < 8; ++ko) {
#pragma unroll
            for (int ki = 0; ki < 16; ++ki) {
                float hk = __ldcg(hp + ki * BATCH);
                ull pa = pk2(hk, hk);
                ulonglong2 w0 = *(const ulonglong2*)(wp + ki * 32);
                ulonglong2 w1 = *(const ulonglong2*)(wp + ki * 32 + 4);
                a0 = ffma2(pa, w0.x, a0);
                a1 = ffma2(pa, w0.y, a1);
                a2 = ffma2(pa, w1.x, a2);
                a3 = ffma2(pa, w1.y, a3);
            }
            hp += 16 * BATCH;
            wp += 16 * 32;
        }
        float* rp = red + (q * 16 + b) * 36 + jg * 8;
        *(ulonglong2*)rp       = make_ulonglong2(a0, a1);
        *(ulonglong2*)(rp + 4) = make_ulonglong2(a2, a3);
        __syncthreads();

        float s = xv;
#pragma unroll
        for (int qq = 0; qq < 8; ++qq) s += red[(qq * 16 + rb) * 36 + rj];
        lastv = tanhf(s);
        __stcg(g_h[cur ^ 1] + houto, lastv);

        // ---- grid-wide barrier (monotonic counter, reset per launch) ----
        expected += NBLK;
        __threadfence();          // release h store to L2
        __syncthreads();          // red reads done + all stores fenced
        if (tid == 0) {
            atomicAdd(&g_bar, 1u);
            while (*(volatile unsigned*)&g_bar < expected) { }
        }
        __syncthreads();
        cur ^= 1;
    }
    out[(size_t)(bt * 16 + rb) * HIDDEN + jt * 32 + rj] = lastv;
}

// ---------------------------------------------------------------------------
extern "C" void kernel_launch(void* const* d_in, const int* in_sizes, int n_in,
                              void* d_out, int out_size)
{
    const int*   src = (const int*)  d_in[0];
    const float* emb = (const float*)d_in[1];
    const float* Wxh = (const float*)d_in[2];
    const float* bxh = (const float*)d_in[3];
    const float* Whh = (const float*)d_in[4];
    float* out = (float*)d_out;

    static int smem_set = 0;
    const int scan_smem = (32768 + 8 * 16 * 36) * sizeof(float);   // 149504 B
    if (!smem_set) {
        cudaFuncSetAttribute(rnn_scan_kernel,
                             cudaFuncAttributeMaxDynamicSharedMemorySize, scan_smem);
        smem_set = 1;
    }

    init_kernel<<<256, 256>>>();
    xproj_kernel<<<dim3(8, SRC_LEN), 256>>>(src, emb, Wxh, bxh);
    rnn_scan_kernel<<<NBLK, 512, scan_smem>>>(Whh, out);
}